// round 15
// baseline (speedup 1.0000x reference)
#include <cuda_runtime.h>
#include <math_constants.h>

#define HH 512
#define WW 1024
#define NPIX (HH * WW)      // 524288 = 2^19
#define KNB 15
#define GAMMA_F 0.1f

#define P2_BLOCK 256
#define P2_GRID  (NPIX / P2_BLOCK)   // 2048
#define TILE 5
#define NTILE (KNB / TILE)            // 3

// Packed per-pixel data, 16 bytes: (s, nx, ny, nz).
__device__ float4 g_packed[NPIX];
__device__ float  g_partials[P2_GRID];
__device__ unsigned int g_done_ctr;

// Direction from pixel index (ERP grid), fast intrinsics.
__device__ __forceinline__ void erp_dir(int i, float& dx, float& dy, float& dz) {
    int row = i >> 10;          // W = 1024
    int col = i & 1023;
    float lat = 0.5f * CUDART_PI_F - (row + 0.5f) * (CUDART_PI_F / HH);
    float lon = (col + 0.5f) * (2.0f * CUDART_PI_F / WW) - CUDART_PI_F;
    float sla = __sinf(lat), cla = __cosf(lat);
    float slo = __sinf(lon), clo = __cosf(lon);
    dx = cla * slo;
    dy = sla;
    dz = cla * clo;
}

// ---------------- Pass 1: interleave {s, nx, ny, nz} ----------------
__global__ void __launch_bounds__(256) pack_kernel(const float* __restrict__ sig1,
                                                   const float* __restrict__ sig2) {
    if (blockIdx.x == 0 && threadIdx.x == 0) g_done_ctr = 0;

    int i = blockIdx.x * 256 + threadIdx.x;
    float s  = __ldcs(&sig1[i]);
    float nx = __ldcs(&sig2[i]);
    float ny = __ldcs(&sig2[NPIX + i]);
    float nz = __ldcs(&sig2[2 * NPIX + i]);
    g_packed[i] = make_float4(s, nx, ny, nz);
}

// ---------------- Pass 2: loss with smem-staged indices ----------------
// All 15 neighbour indices loaded up front into SHARED memory: gather addresses
// have zero in-loop global-latency dependence, while the freed registers allow
// 5 CTAs/SM (40 warps) -> outstanding gather sectors ~= 40*5 = 200/SM.
__global__ void __launch_bounds__(P2_BLOCK, 5) loss_kernel(const float* __restrict__ weights,
                                                           const int* __restrict__ nb,
                                                           float* __restrict__ out) {
    __shared__ int s_idx[KNB][P2_BLOCK];   // 15 KB; [k][tid] -> conflict-free LDS

    int i = blockIdx.x * P2_BLOCK + threadIdx.x;
    int tid = threadIdx.x;

    // Stage ALL 15 neighbour indices (15 independent coalesced LDGs, then STS)
#pragma unroll
    for (int k = 0; k < KNB; k++)
        s_idx[k][tid] = __ldcs(&nb[k * NPIX + i]) & (NPIX - 1);

    // Own pixel (coalesced 16B load + analytic direction)
    float4 E = g_packed[i];
    float dix, diy, diz;
    erp_dir(i, dix, diy, diz);
    float nix = E.y, niy = E.z, niz = E.w;
    float pn_i = E.x * (dix * nix + diy * niy + diz * niz);

    float acc1 = 0.0f;   // sum_k (aux1*w)^2
    float acc2 = 0.0f;   // sum_k aux2*w

#pragma unroll
    for (int t = 0; t < NTILE; t++) {
        // Tile indices from smem (29-cyc LDS, no global dependence)
        int idx[TILE];
#pragma unroll
        for (int u = 0; u < TILE; u++)
            idx[u] = s_idx[t * TILE + u][tid];

        // 5 gathers in flight simultaneously (one LDG.128 each)
        float4 e[TILE];
#pragma unroll
        for (int u = 0; u < TILE; u++)
            e[u] = __ldg(&g_packed[idx[u]]);

        // Weights for this tile (coalesced, evict-first)
        float wv[TILE];
#pragma unroll
        for (int u = 0; u < TILE; u++)
            wv[u] = __ldcs(&weights[(t * TILE + u) * NPIX + i]);

        // Math
#pragma unroll
        for (int u = 0; u < TILE; u++) {
            float djx, djy, djz;
            erp_dir(idx[u], djx, djy, djz);

            float dotpn = e[u].x * (djx * nix + djy * niy + djz * niz);
            float aux1 = pn_i - dotpn;

            float ddx = nix - e[u].y;
            float ddy = niy - e[u].z;
            float ddz = niz - e[u].w;
            float aux2 = sqrtf(ddx * ddx + ddy * ddy + ddz * ddz);

            float tt = aux1 * wv[u];
            acc1 += tt * tt;
            acc2 += aux2 * wv[u];
        }
    }

    float v = sqrtf(acc1) + GAMMA_F * acc2;

    // Deterministic block tree-reduce (reuse the index smem as scratch)
    float* sm = (float*)&s_idx[0][0];
    __syncthreads();                 // everyone done with s_idx
    sm[tid] = v;
    __syncthreads();
#pragma unroll
    for (int s = P2_BLOCK / 2; s > 0; s >>= 1) {
        if (tid < s) sm[tid] += sm[tid + s];
        __syncthreads();
    }

    __shared__ bool amLast;
    if (tid == 0) {
        g_partials[blockIdx.x] = sm[0];
        __threadfence();
        unsigned int prev = atomicAdd(&g_done_ctr, 1u);
        amLast = (prev == P2_GRID - 1);
    }
    __syncthreads();

    // Last block: fixed-order tree reduce over all partials (bit-deterministic)
    if (amLast) {
        float acc = 0.0f;
#pragma unroll
        for (int p = tid; p < P2_GRID; p += P2_BLOCK)
            acc += __ldcg(&g_partials[p]);
        sm[tid] = acc;
        __syncthreads();
#pragma unroll
        for (int s = P2_BLOCK / 2; s > 0; s >>= 1) {
            if (tid < s) sm[tid] += sm[tid + s];
            __syncthreads();
        }
        if (tid == 0)
            out[0] = sm[0] * (1.0f / (float)NPIX);   // MULTIPLIER = 1.0
    }
}

extern "C" void kernel_launch(void* const* d_in, const int* in_sizes, int n_in,
                              void* d_out, int out_size) {
    const float* sig1    = (const float*)d_in[0];   // N f32
    const float* sig2    = (const float*)d_in[1];   // 3N f32
    const float* weights = (const float*)d_in[2];   // K*N f32
    const int*   nb      = (const int*)d_in[3];     // K*N int32
    float* out = (float*)d_out;

    pack_kernel<<<NPIX / 256, 256>>>(sig1, sig2);
    loss_kernel<<<P2_GRID, P2_BLOCK>>>(weights, nb, out);
}